// round 2
// baseline (speedup 1.0000x reference)
#include <cuda_runtime.h>
#include <cstdint>
#include <cstddef>

// MPS chain contraction, 32768 elements, 221 steps of 3x3 matrices.
// v_out = e0^T * M_1 * ... * M_221,  M_l = I(bias) + sum_d x[l,d] * T[l,:,:,d]
//
// Round-2 design: 4-way chain split via associativity.
//  - Each element-pair (2 elems packed as f32x2) is handled by 4 threads,
//    one per chain segment (56/55/55/55 steps). Each computes a 3x3 partial
//    product P_s in matrix form (54 f32x2 FMA/step), then one thread combines.
//  - 256 blocks x 256 threads (t = s*64 + p): 65536 threads = 2048 warps
//    -> ~4 warps/SMSP at 2 blocks/SM (vs 1 before).
//  - X staged via 4B cp.async, 14 double-buffered chunks of 4 steps.
//  - T staged once, duplicated (t,t) pairs, rows padded to 10 u64 so each
//    3x3x3 step reads as 4x ld.shared.v2.u64 + 1x ld.shared.b64 per row.

typedef unsigned long long u64;

#define NSTEPS  221
#define NSEG    4
#define CH      4            // steps per chunk
#define NCH     14           // chunks (covers 56 staged steps per segment)
#define PPB     64           // element pairs per block
#define EPB     128          // elements per block
#define BT      256          // threads per block (4 segs * 64 pairs)
#define NBLK    256          // 32768 / 128
#define ESTRIDE 693          // floats per element

#define XBUF_U64 (NSEG * CH * 3 * PPB)    // 3072 u64 per buffer
#define TSTRIDE  30                        // padded u64 per step (3 rows x 10)
#define T_U64    (NSTEPS * TSTRIDE)        // 6630
#define SMEM_U64 (2 * XBUF_U64 + T_U64)    // 12774
#define SMEM_BYTES (SMEM_U64 * 8)          // 102192 B -> 2 blocks/SM

__device__ __forceinline__ u64 f2fma(u64 a, u64 b, u64 c) {
    u64 d; asm("fma.rn.f32x2 %0, %1, %2, %3;" : "=l"(d) : "l"(a), "l"(b), "l"(c)); return d;
}
__device__ __forceinline__ u64 f2mul(u64 a, u64 b) {
    u64 d; asm("mul.rn.f32x2 %0, %1, %2;" : "=l"(d) : "l"(a), "l"(b)); return d;
}
__device__ __forceinline__ u64 dup2(float v) {
    u64 d; asm("mov.b64 %0, {%1, %1};" : "=l"(d) : "f"(v)); return d;
}
__device__ __forceinline__ void unpack2(u64 v, float& lo, float& hi) {
    asm("mov.b64 {%0, %1}, %2;" : "=f"(lo), "=f"(hi) : "l"(v));
}
__device__ __forceinline__ void lds2(u64& a, u64& b, uint32_t addr) {
    asm("ld.shared.v2.u64 {%0, %1}, [%2];" : "=l"(a), "=l"(b) : "r"(addr));
}
__device__ __forceinline__ u64 lds1(uint32_t addr) {
    u64 a; asm("ld.shared.b64 %0, [%1];" : "=l"(a) : "r"(addr)); return a;
}
__device__ __forceinline__ void cpa4(uint32_t dst, const float* src) {
    asm volatile("cp.async.ca.shared.global [%0], [%1], 4;" :: "r"(dst), "l"(src) : "memory");
}
__device__ __forceinline__ void cpcommit() {
    asm volatile("cp.async.commit_group;" ::: "memory");
}
template <int N> __device__ __forceinline__ void cpwait() {
    asm volatile("cp.async.wait_group %0;" :: "n"(N) : "memory");
}

extern __shared__ u64 smem_u64[];

// Stage chunk c: for all 128 elems x 4 segments, 12 floats (4 steps) each.
// i = (eq*4 + s)*12 + j: lanes walk 12 consecutive floats of one (elem, seg).
__device__ __forceinline__ void stage_chunk(const float* __restrict__ samples,
                                            int e0, int c, uint32_t xb, int tid) {
    const float* sb = samples + (size_t)e0 * ESTRIDE + c * (CH * 3);
    int j = tid % 12;
    int r = tid / 12;
    #pragma unroll
    for (int k = 0; k < (NSEG * EPB * CH * 3) / BT; k++) {   // 24 iters
        int s  = r & 3;
        int eq = r >> 2;                 // local element 0..127
        int segoff = s * 165 + (s != 0) * 3;  // (55*s + (s>0)) * 3
        const float* src = sb + (size_t)eq * ESTRIDE + segoff + j;
        uint32_t dst = xb + (uint32_t)(s * 6144 + j * 512 + (eq >> 1) * 8 + (eq & 1) * 4);
        cpa4(dst, src);
        j += 4; r += 21;
        if (j >= 12) { j -= 12; r += 1; }
    }
    cpcommit();
}

__global__ void __launch_bounds__(BT, 2)
mps_kernel(const float* __restrict__ samples,
           const float* __restrict__ T1,
           const float* __restrict__ bias,
           float* __restrict__ out)
{
    const int tid = threadIdx.x;
    const int s   = tid >> 6;     // segment 0..3
    const int p   = tid & 63;     // element pair 0..63
    const int e0  = blockIdx.x * EPB;

    u64* Tsh = smem_u64 + 2 * XBUF_U64;
    uint32_t xbase0 = (uint32_t)__cvta_generic_to_shared(smem_u64);
    uint32_t xbase1 = xbase0 + XBUF_U64 * 8;
    uint32_t tbase  = xbase0 + 2 * XBUF_U64 * 8;

    // Stage T, duplicated, layout [l][k(pad 10)][j*3+d].
    for (int i = tid; i < NSTEPS * 27; i += BT) {
        int l = i / 27, kd = i % 27;
        int k = kd / 9, jd = kd % 9;
        float v = T1[i];
        Tsh[l * TSTRIDE + k * 10 + jd] = dup2(v);
    }

    // Bias pairs (bias is [3,3]; identity in practice but handled generally).
    u64 Bp[9];
    #pragma unroll
    for (int j = 0; j < 9; j++) Bp[j] = dup2(bias[j]);

    stage_chunk(samples, e0, 0, xbase0, tid);

    // Partial product P = identity + bias-free start: P starts as identity.
    u64 P[9];
    const u64 ONE2 = dup2(1.0f), ZERO2 = dup2(0.0f);
    #pragma unroll
    for (int j = 0; j < 9; j++) P[j] = (j % 4 == 0) ? ONE2 : ZERO2;

    const int lbase = 55 * s + (s != 0);    // first step of this segment

    for (int c = 0; c < NCH; c++) {
        if (c + 1 < NCH) {
            stage_chunk(samples, e0, c + 1, ((c + 1) & 1) ? xbase1 : xbase0, tid);
            cpwait<1>();
        } else {
            cpwait<0>();
        }
        __syncthreads();

        uint32_t xaddr = ((c & 1) ? xbase1 : xbase0) + (uint32_t)(s * 6144 + p * 8);
        const int nst = (c == NCH - 1 && s != 0) ? 3 : 4;   // segs 1-3 have 55 steps

        #pragma unroll
        for (int st = 0; st < CH; st++) {
            if (st >= nst) break;
            u64 X0 = lds1(xaddr + (st * 3 + 0) * 512);
            u64 X1 = lds1(xaddr + (st * 3 + 1) * 512);
            u64 X2 = lds1(xaddr + (st * 3 + 2) * 512);
            uint32_t taddr = tbase + (uint32_t)((lbase + c * CH + st) * (TSTRIDE * 8));

            u64 M[9];
            #pragma unroll
            for (int k = 0; k < 3; k++) {
                u64 t0,t1,t2,t3,t4,t5,t6,t7,t8;
                uint32_t ra = taddr + k * 80;
                lds2(t0, t1, ra);
                lds2(t2, t3, ra + 16);
                lds2(t4, t5, ra + 32);
                lds2(t6, t7, ra + 48);
                t8 = lds1(ra + 64);
                M[k*3+0] = f2fma(X2, t2, f2fma(X1, t1, f2fma(X0, t0, Bp[k*3+0])));
                M[k*3+1] = f2fma(X2, t5, f2fma(X1, t4, f2fma(X0, t3, Bp[k*3+1])));
                M[k*3+2] = f2fma(X2, t8, f2fma(X1, t7, f2fma(X0, t6, Bp[k*3+2])));
            }
            u64 Pn[9];
            #pragma unroll
            for (int i = 0; i < 3; i++) {
                #pragma unroll
                for (int j = 0; j < 3; j++) {
                    Pn[i*3+j] = f2fma(P[i*3+0], M[0*3+j],
                                f2fma(P[i*3+1], M[1*3+j],
                                f2mul(P[i*3+2], M[2*3+j])));
                }
            }
            #pragma unroll
            for (int j = 0; j < 9; j++) P[j] = Pn[j];
        }
        __syncthreads();
    }

    // Combine: Cbuf overlays the X buffers (all compute done, barrier above).
    u64* Cb = smem_u64;
    if (s != 0) {
        #pragma unroll
        for (int j = 0; j < 9; j++) Cb[p * 27 + (s - 1) * 9 + j] = P[j];
    }
    __syncthreads();

    if (s == 0) {
        // v = row 0 of P0, then v = v*P1*P2*P3.
        u64 r0 = P[0], r1 = P[1], r2 = P[2];
        const u64* cpb = Cb + p * 27;
        #pragma unroll
        for (int ss = 0; ss < 3; ss++) {
            const u64* m = cpb + ss * 9;
            u64 n0 = f2fma(r2, m[6], f2fma(r1, m[3], f2mul(r0, m[0])));
            u64 n1 = f2fma(r2, m[7], f2fma(r1, m[4], f2mul(r0, m[1])));
            u64 n2 = f2fma(r2, m[8], f2fma(r1, m[5], f2mul(r0, m[2])));
            r0 = n0; r1 = n1; r2 = n2;
        }
        float a0,b0,a1,b1,a2,b2;
        unpack2(r0, a0, b0);
        unpack2(r1, a1, b1);
        unpack2(r2, a2, b2);
        float* oA = out + (size_t)(e0 + 2 * p) * 3;
        oA[0] = a0; oA[1] = a1; oA[2] = a2;
        oA[3] = b0; oA[4] = b1; oA[5] = b2;
    }
}

extern "C" void kernel_launch(void* const* d_in, const int* in_sizes, int n_in,
                              void* d_out, int out_size) {
    (void)in_sizes; (void)n_in; (void)out_size;
    const float* samples = (const float*)d_in[0];
    const float* tensors = (const float*)d_in[1];
    const float* bias    = (const float*)d_in[2];
    float* out = (float*)d_out;

    cudaFuncSetAttribute(mps_kernel, cudaFuncAttributeMaxDynamicSharedMemorySize, SMEM_BYTES);
    mps_kernel<<<NBLK, BT, SMEM_BYTES>>>(samples, tensors, bias, out);
}

// round 4
// speedup vs baseline: 1.4648x; 1.4648x over previous
#include <cuda_runtime.h>
#include <cstdint>
#include <cstddef>

// MPS chain contraction, 32768 elements, 221 steps of 3x3 matrices.
// v_out = e0^T * M_1 * ... * M_221,  M_l = bias + sum_d x[l,d] * T[l,:,:,d]
//
// Round-4: same as round 3 (4-way chain split, f32x2 element pairs,
// double-buffered cp.async staging, bank-skewed transposed smem layout)
// but ROWB = 520 (8-byte pad) instead of 516: keeps every ld.shared.b64
// 8B-aligned (516 trapped with "misaligned address") while still skewing
// banks: write conflicts drop from 12..32-way (R1/R2) to ~2-way.

typedef unsigned long long u64;

#define NSTEPS  221
#define NSEG    4
#define CH      4            // steps per chunk
#define NCH     14           // chunks (covers 56 staged steps per segment)
#define PPB     64           // element pairs per block
#define EPB     128          // elements per block
#define BT      256          // threads per block (4 segs * 64 pairs)
#define NBLK    256          // 32768 / 128
#define ESTRIDE 693          // floats per element

// Padded staging layout (bytes):
//   buffer -> segment s at s*SEGB -> row f (0..11) at f*ROWB -> pair p at p*8
#define ROWB       520                      // 64*8 + 8 pad (bank skew, 8B aligned)
#define SEGB       (12 * ROWB)              // 6240
#define XBUF_BYTES (NSEG * SEGB)            // 24960
#define TSTRIDE    30                       // padded u64 per step (3 rows x 10)
#define T_U64      (NSTEPS * TSTRIDE)       // 6630
#define SMEM_BYTES (2 * XBUF_BYTES + T_U64 * 8)   // 49920 + 53040 = 102960

__device__ __forceinline__ u64 f2fma(u64 a, u64 b, u64 c) {
    u64 d; asm("fma.rn.f32x2 %0, %1, %2, %3;" : "=l"(d) : "l"(a), "l"(b), "l"(c)); return d;
}
__device__ __forceinline__ u64 f2mul(u64 a, u64 b) {
    u64 d; asm("mul.rn.f32x2 %0, %1, %2;" : "=l"(d) : "l"(a), "l"(b)); return d;
}
__device__ __forceinline__ u64 dup2(float v) {
    u64 d; asm("mov.b64 %0, {%1, %1};" : "=l"(d) : "f"(v)); return d;
}
__device__ __forceinline__ void unpack2(u64 v, float& lo, float& hi) {
    asm("mov.b64 {%0, %1}, %2;" : "=f"(lo), "=f"(hi) : "l"(v));
}
__device__ __forceinline__ void lds2(u64& a, u64& b, uint32_t addr) {
    asm("ld.shared.v2.u64 {%0, %1}, [%2];" : "=l"(a), "=l"(b) : "r"(addr));
}
__device__ __forceinline__ u64 lds1(uint32_t addr) {
    u64 a; asm("ld.shared.b64 %0, [%1];" : "=l"(a) : "r"(addr)); return a;
}
__device__ __forceinline__ void cpa4(uint32_t dst, const float* src) {
    asm volatile("cp.async.ca.shared.global [%0], [%1], 4;" :: "r"(dst), "l"(src) : "memory");
}
__device__ __forceinline__ void cpcommit() {
    asm volatile("cp.async.commit_group;" ::: "memory");
}
template <int N> __device__ __forceinline__ void cpwait() {
    asm volatile("cp.async.wait_group %0;" :: "n"(N) : "memory");
}

extern __shared__ u64 smem_u64[];

// Stage chunk c: for all 128 elems x 4 segments, 12 floats (4 steps) each.
// Linear index i = (eq*4 + s)*12 + j ; lanes walk 12 consecutive floats of
// one (elem, seg) run -> global side ~coalesced; smem side bank-skewed.
__device__ __forceinline__ void stage_chunk(const float* __restrict__ samples,
                                            int e0, int c, uint32_t xb, int tid) {
    const float* sb = samples + (size_t)e0 * ESTRIDE + c * (CH * 3);
    int j = tid % 12;
    int r = tid / 12;
    #pragma unroll
    for (int k = 0; k < (NSEG * EPB * CH * 3) / BT; k++) {   // 24 iters
        int s  = r & 3;
        int eq = r >> 2;                      // local element 0..127
        int segoff = s * 165 + (s != 0) * 3;  // float offset of segment start
        const float* src = sb + (size_t)eq * ESTRIDE + segoff + j;
        uint32_t dst = xb + (uint32_t)(s * SEGB + j * ROWB + (eq >> 1) * 8 + (eq & 1) * 4);
        cpa4(dst, src);
        j += 4; r += 21;
        if (j >= 12) { j -= 12; r += 1; }
    }
    cpcommit();
}

__global__ void __launch_bounds__(BT, 2)
mps_kernel(const float* __restrict__ samples,
           const float* __restrict__ T1,
           const float* __restrict__ bias,
           float* __restrict__ out)
{
    const int tid = threadIdx.x;
    const int s   = tid >> 6;     // segment 0..3
    const int p   = tid & 63;     // element pair 0..63
    const int e0  = blockIdx.x * EPB;

    u64* Tsh = smem_u64 + (2 * XBUF_BYTES) / 8;
    uint32_t xbase0 = (uint32_t)__cvta_generic_to_shared(smem_u64);
    uint32_t xbase1 = xbase0 + XBUF_BYTES;
    uint32_t tbase  = xbase0 + 2 * XBUF_BYTES;

    // Stage T, duplicated (t,t), layout [l][k(pad 10)][j*3+d].
    for (int i = tid; i < NSTEPS * 27; i += BT) {
        int l = i / 27, kd = i % 27;
        int k = kd / 9, jd = kd % 9;
        float v = T1[i];
        Tsh[l * TSTRIDE + k * 10 + jd] = dup2(v);
    }

    u64 Bp[9];
    #pragma unroll
    for (int j = 0; j < 9; j++) Bp[j] = dup2(bias[j]);

    stage_chunk(samples, e0, 0, xbase0, tid);

    // Partial product P starts as identity.
    u64 P[9];
    const u64 ONE2 = dup2(1.0f), ZERO2 = dup2(0.0f);
    #pragma unroll
    for (int j = 0; j < 9; j++) P[j] = (j % 4 == 0) ? ONE2 : ZERO2;

    const int lbase = 55 * s + (s != 0);    // first step of this segment

    for (int c = 0; c < NCH; c++) {
        if (c + 1 < NCH) {
            stage_chunk(samples, e0, c + 1, ((c + 1) & 1) ? xbase1 : xbase0, tid);
            cpwait<1>();
        } else {
            cpwait<0>();
        }
        __syncthreads();

        uint32_t xaddr = ((c & 1) ? xbase1 : xbase0) + (uint32_t)(s * SEGB + p * 8);
        const int nst = (c == NCH - 1 && s != 0) ? 3 : 4;   // segs 1-3: 55 steps

        #pragma unroll
        for (int st = 0; st < CH; st++) {
            if (st >= nst) break;
            u64 X0 = lds1(xaddr + (st * 3 + 0) * ROWB);
            u64 X1 = lds1(xaddr + (st * 3 + 1) * ROWB);
            u64 X2 = lds1(xaddr + (st * 3 + 2) * ROWB);
            uint32_t taddr = tbase + (uint32_t)((lbase + c * CH + st) * (TSTRIDE * 8));

            u64 M[9];
            #pragma unroll
            for (int k = 0; k < 3; k++) {
                u64 t0,t1,t2,t3,t4,t5,t6,t7,t8;
                uint32_t ra = taddr + k * 80;
                lds2(t0, t1, ra);
                lds2(t2, t3, ra + 16);
                lds2(t4, t5, ra + 32);
                lds2(t6, t7, ra + 48);
                t8 = lds1(ra + 64);
                M[k*3+0] = f2fma(X2, t2, f2fma(X1, t1, f2fma(X0, t0, Bp[k*3+0])));
                M[k*3+1] = f2fma(X2, t5, f2fma(X1, t4, f2fma(X0, t3, Bp[k*3+1])));
                M[k*3+2] = f2fma(X2, t8, f2fma(X1, t7, f2fma(X0, t6, Bp[k*3+2])));
            }
            u64 Pn[9];
            #pragma unroll
            for (int i = 0; i < 3; i++) {
                #pragma unroll
                for (int j = 0; j < 3; j++) {
                    Pn[i*3+j] = f2fma(P[i*3+0], M[0*3+j],
                                f2fma(P[i*3+1], M[1*3+j],
                                f2mul(P[i*3+2], M[2*3+j])));
                }
            }
            #pragma unroll
            for (int j = 0; j < 9; j++) P[j] = Pn[j];
        }
        __syncthreads();
    }

    // Combine: reuse X buffers as scratch (all compute done, barrier above).
    u64* Cb = smem_u64;
    if (s != 0) {
        #pragma unroll
        for (int j = 0; j < 9; j++) Cb[p * 27 + (s - 1) * 9 + j] = P[j];
    }
    __syncthreads();

    if (s == 0) {
        // v = row 0 of P0, then v = v*P1*P2*P3.
        u64 r0 = P[0], r1 = P[1], r2 = P[2];
        const u64* cpb = Cb + p * 27;
        #pragma unroll
        for (int ss = 0; ss < 3; ss++) {
            const u64* m = cpb + ss * 9;
            u64 n0 = f2fma(r2, m[6], f2fma(r1, m[3], f2mul(r0, m[0])));
            u64 n1 = f2fma(r2, m[7], f2fma(r1, m[4], f2mul(r0, m[1])));
            u64 n2 = f2fma(r2, m[8], f2fma(r1, m[5], f2mul(r0, m[2])));
            r0 = n0; r1 = n1; r2 = n2;
        }
        float a0,b0,a1,b1,a2,b2;
        unpack2(r0, a0, b0);
        unpack2(r1, a1, b1);
        unpack2(r2, a2, b2);
        float* oA = out + (size_t)(e0 + 2 * p) * 3;
        oA[0] = a0; oA[1] = a1; oA[2] = a2;
        oA[3] = b0; oA[4] = b1; oA[5] = b2;
    }
}

extern "C" void kernel_launch(void* const* d_in, const int* in_sizes, int n_in,
                              void* d_out, int out_size) {
    (void)in_sizes; (void)n_in; (void)out_size;
    const float* samples = (const float*)d_in[0];
    const float* tensors = (const float*)d_in[1];
    const float* bias    = (const float*)d_in[2];
    float* out = (float*)d_out;

    cudaFuncSetAttribute(mps_kernel, cudaFuncAttributeMaxDynamicSharedMemorySize, SMEM_BYTES);
    mps_kernel<<<NBLK, BT, SMEM_BYTES>>>(samples, tensors, bias, out);
}